// round 8
// baseline (speedup 1.0000x reference)
#include <cuda_runtime.h>
#include <cuda_fp16.h>
#include <cstdint>
#include <cstddef>

#define NN 4096   // nodes
#define DD 128    // embedding dim
#define RR 8      // relations
#define OO 128    // output dim
#define NB 4096   // batch

// ---- pass 1 (legacy tf32 split) config ----
#define BM 128
#define BK 32
#define PAD_A 36
#define PAD_B 136

// ---- pass 2 (fp16 m16n8k16) config ----
#define BK2 32
#define SW 40          // smem row stride in halves (80 bytes) -> conflict-free frags

// scratch (device globals: no allocations allowed)
__device__ float g_W[(size_t)RR * NN * OO];      // pass1 out: W[r][k][n] fp32 (16 MB)
__device__ float g_part[(size_t)RR * NN * OO];   // pass2 out (16 MB)
__device__ __half g_Wth[(size_t)RR * OO * NN];   // W^T hi fp16: [r][n][k] (8 MB)
__device__ __half g_Wtl[(size_t)RR * OO * NN];   // W^T lo fp16: [r][n][k] (8 MB)

__device__ __forceinline__ float rna_tf32(float x) {
    uint32_t u;
    asm("cvt.rna.tf32.f32 %0, %1;" : "=r"(u) : "f"(x));
    return __uint_as_float(u);
}

// ============ pass 2: fp16 tensor-core GEMM (B hi/lo split, 2 terms) ============
// C[r][mtile] = adj[r] (128 x 4096 fp32 -> fp16 rn) @ W[r] (4096x128, pre-split fp16)
__global__ __launch_bounds__(256, 2)
void gemm_fp16_split_kernel(const float* __restrict__ adj,
                            const __half* __restrict__ Bth,
                            const __half* __restrict__ Btl,
                            float* __restrict__ Cout) {
    __shared__ __align__(16) __half As[128 * SW];   // 10240 B
    __shared__ __align__(16) __half Bh[128 * SW];   // 10240 B  (n-major, k contiguous)
    __shared__ __align__(16) __half Bl[128 * SW];   // 10240 B

    const int tid  = threadIdx.x;
    const int lane = tid & 31;
    const int warp = tid >> 5;
    const int wm   = warp >> 2;   // 0..1 : 64 rows
    const int wn   = warp & 3;    // 0..3 : 32 cols
    const int grp  = lane >> 2;   // 0..7
    const int tig  = lane & 3;    // 0..3

    const int mtile = blockIdx.x;
    const int r     = blockIdx.y;
    const float* Ag = adj + ((size_t)r * NN + (size_t)mtile * 128) * NN;
    const __half* Bhg = Bth + (size_t)r * OO * NN;
    const __half* Blg = Btl + (size_t)r * OO * NN;
    float* Cg = Cout + ((size_t)r * NN + (size_t)mtile * 128) * OO;

    float acc[4][4][4];
#pragma unroll
    for (int i = 0; i < 4; i++)
#pragma unroll
        for (int j = 0; j < 4; j++) {
            acc[i][j][0] = 0.f; acc[i][j][1] = 0.f;
            acc[i][j][2] = 0.f; acc[i][j][3] = 0.f;
        }

    float4 ra[4];       // A stage: 128x32 fp32 / 256 thr = 4 float4
    uint4  rbh[2], rbl[2]; // B stage: 128x32 fp16 / 256 thr = 2 uint4 per buffer

    // prologue: k-tile 0
#pragma unroll
    for (int j = 0; j < 4; j++) {
        int fi  = tid + j * 256;       // 0..1023
        int row = fi >> 3;             // 0..127
        int c4  = fi & 7;              // float4 within 32-k row
        ra[j] = *reinterpret_cast<const float4*>(Ag + (size_t)row * NN + c4 * 4);
    }
#pragma unroll
    for (int j = 0; j < 2; j++) {
        int fi = tid + j * 256;        // 0..511
        int n  = fi >> 2;              // 0..127
        int c8 = fi & 3;               // uint4 (8 fp16) within 32-k row
        size_t go = (size_t)n * NN + c8 * 8;
        rbh[j] = *reinterpret_cast<const uint4*>(Bhg + go);
        rbl[j] = *reinterpret_cast<const uint4*>(Blg + go);
    }

    const int KT = NN / BK2;   // 128
#pragma unroll 1
    for (int kt = 0; kt < KT; ++kt) {
        __syncthreads();
        // STS: A converts fp32 -> fp16 rn
#pragma unroll
        for (int j = 0; j < 4; j++) {
            int fi  = tid + j * 256;
            int row = fi >> 3;
            int c4  = fi & 7;
            __half2 p01 = __floats2half2_rn(ra[j].x, ra[j].y);
            __half2 p23 = __floats2half2_rn(ra[j].z, ra[j].w);
            *reinterpret_cast<__half2*>(&As[row * SW + c4 * 4])     = p01;
            *reinterpret_cast<__half2*>(&As[row * SW + c4 * 4 + 2]) = p23;
        }
#pragma unroll
        for (int j = 0; j < 2; j++) {
            int fi = tid + j * 256;
            int n  = fi >> 2;
            int c8 = fi & 3;
            *reinterpret_cast<uint4*>(&Bh[n * SW + c8 * 8]) = rbh[j];
            *reinterpret_cast<uint4*>(&Bl[n * SW + c8 * 8]) = rbl[j];
        }
        __syncthreads();
        if (kt + 1 < KT) {   // prefetch next tile into regs while computing
            const float* Ak = Ag + (kt + 1) * BK2;
#pragma unroll
            for (int j = 0; j < 4; j++) {
                int fi  = tid + j * 256;
                int row = fi >> 3;
                int c4  = fi & 7;
                ra[j] = *reinterpret_cast<const float4*>(Ak + (size_t)row * NN + c4 * 4);
            }
#pragma unroll
            for (int j = 0; j < 2; j++) {
                int fi = tid + j * 256;
                int n  = fi >> 2;
                int c8 = fi & 3;
                size_t go = (size_t)n * NN + (size_t)(kt + 1) * BK2 + c8 * 8;
                rbh[j] = *reinterpret_cast<const uint4*>(Bhg + go);
                rbl[j] = *reinterpret_cast<const uint4*>(Blg + go);
            }
        }
        // compute: 2 k16-steps
#pragma unroll
        for (int ks = 0; ks < 2; ++ks) {
            uint32_t af[4][4], bfh[4][2], bfl[4][2];
#pragma unroll
            for (int mi = 0; mi < 4; mi++) {
                const char* p = (const char*)As
                    + (wm * 64 + mi * 16 + grp) * (SW * 2) + ks * 32 + tig * 4;
                af[mi][0] = *(const uint32_t*)(p);                 // rows grp,   k 2tig..+1
                af[mi][1] = *(const uint32_t*)(p + 8 * SW * 2);    // rows grp+8
                af[mi][2] = *(const uint32_t*)(p + 16);            // k +8
                af[mi][3] = *(const uint32_t*)(p + 8 * SW * 2 + 16);
            }
#pragma unroll
            for (int ni = 0; ni < 4; ni++) {
                int boff = (wn * 32 + ni * 8 + grp) * (SW * 2) + ks * 32 + tig * 4;
                bfh[ni][0] = *(const uint32_t*)((const char*)Bh + boff);
                bfh[ni][1] = *(const uint32_t*)((const char*)Bh + boff + 16);
                bfl[ni][0] = *(const uint32_t*)((const char*)Bl + boff);
                bfl[ni][1] = *(const uint32_t*)((const char*)Bl + boff + 16);
            }
#pragma unroll
            for (int mi = 0; mi < 4; mi++)
#pragma unroll
                for (int ni = 0; ni < 4; ni++) {
                    asm volatile(
                        "mma.sync.aligned.m16n8k16.row.col.f32.f16.f16.f32 "
                        "{%0,%1,%2,%3}, {%4,%5,%6,%7}, {%8,%9}, {%0,%1,%2,%3};\n"
                        : "+f"(acc[mi][ni][0]), "+f"(acc[mi][ni][1]),
                          "+f"(acc[mi][ni][2]), "+f"(acc[mi][ni][3])
                        : "r"(af[mi][0]), "r"(af[mi][1]), "r"(af[mi][2]), "r"(af[mi][3]),
                          "r"(bfh[ni][0]), "r"(bfh[ni][1]));
                    asm volatile(
                        "mma.sync.aligned.m16n8k16.row.col.f32.f16.f16.f32 "
                        "{%0,%1,%2,%3}, {%4,%5,%6,%7}, {%8,%9}, {%0,%1,%2,%3};\n"
                        : "+f"(acc[mi][ni][0]), "+f"(acc[mi][ni][1]),
                          "+f"(acc[mi][ni][2]), "+f"(acc[mi][ni][3])
                        : "r"(af[mi][0]), "r"(af[mi][1]), "r"(af[mi][2]), "r"(af[mi][3]),
                          "r"(bfl[ni][0]), "r"(bfl[ni][1]));
                }
        }
    }

    // epilogue: disjoint tile store
#pragma unroll
    for (int mi = 0; mi < 4; mi++) {
        int row0 = wm * 64 + mi * 16 + grp;
#pragma unroll
        for (int ni = 0; ni < 4; ni++) {
            int col = wn * 32 + ni * 8 + tig * 2;
            *reinterpret_cast<float2*>(Cg + (size_t)row0 * OO + col) =
                make_float2(acc[mi][ni][0], acc[mi][ni][1]);
            *reinterpret_cast<float2*>(Cg + (size_t)(row0 + 8) * OO + col) =
                make_float2(acc[mi][ni][2], acc[mi][ni][3]);
        }
    }
}

// ============ pass 1.5: transpose W -> [r][n][k], split fp16 hi/lo ============
__global__ void transpose_split_kernel() {
    __shared__ float t[32][33];
    const int k0 = blockIdx.x * 32;
    const int n0 = blockIdx.y * 32;
    const int r  = blockIdx.z;
    const float* W = g_W + (size_t)r * NN * OO;
#pragma unroll
    for (int i = 0; i < 4; ++i) {
        int k = k0 + threadIdx.y + i * 8;
        t[threadIdx.y + i * 8][threadIdx.x] = W[(size_t)k * OO + n0 + threadIdx.x];
    }
    __syncthreads();
#pragma unroll
    for (int i = 0; i < 4; ++i) {
        int n = n0 + threadIdx.y + i * 8;
        float v = t[threadIdx.x][threadIdx.y + i * 8];
        __half h = __float2half_rn(v);
        __half l = __float2half_rn(v - __half2float(h));
        size_t o = ((size_t)r * OO + n) * NN + k0 + threadIdx.x;
        g_Wth[o] = h;
        g_Wtl[o] = l;
    }
}

// ============ pass 1: legacy tf32 split GEMM (W = emb @ rk) ============
__global__ __launch_bounds__(256, 2)
void gemm_tf32_split_kernel(const float* __restrict__ A0, size_t strideAr, size_t lda,
                            const float* __restrict__ B0, size_t strideBr,
                            float* __restrict__ C0, size_t strideCr,
                            int K) {
    extern __shared__ float smemf[];
    float* As = smemf;
    float* Bh = As + BM * PAD_A;
    float* Bl = Bh + BK * PAD_B;

    const int mtile = blockIdx.x;
    const int r = blockIdx.y;
    const float* Ag = A0 + (size_t)r * strideAr + (size_t)mtile * BM * lda;
    const float* Bg = B0 + (size_t)r * strideBr;
    float* Cg = C0 + (size_t)r * strideCr + (size_t)mtile * BM * OO;

    const int tid  = threadIdx.x;
    const int lane = tid & 31;
    const int warp = tid >> 5;
    const int wm   = warp >> 2;
    const int wn   = warp & 3;
    const int grp  = lane >> 2;
    const int tig  = lane & 3;

    float acc[4][4][4];
#pragma unroll
    for (int i = 0; i < 4; i++)
#pragma unroll
        for (int j = 0; j < 4; j++) {
            acc[i][j][0] = 0.f; acc[i][j][1] = 0.f;
            acc[i][j][2] = 0.f; acc[i][j][3] = 0.f;
        }

    float4 ra[4], rb[4];
#pragma unroll
    for (int j = 0; j < 4; j++) {
        int fi = tid + j * 256;
        ra[j] = *reinterpret_cast<const float4*>(Ag + (size_t)(fi >> 3) * lda + ((fi & 7) << 2));
        rb[j] = *reinterpret_cast<const float4*>(Bg + (size_t)(fi >> 5) * OO + ((fi & 31) << 2));
    }

    const int KT = K / BK;
#pragma unroll 1
    for (int kt = 0; kt < KT; ++kt) {
        __syncthreads();
#pragma unroll
        for (int j = 0; j < 4; j++) {
            int fi = tid + j * 256;
            float4 va = ra[j];
            va.x = rna_tf32(va.x); va.y = rna_tf32(va.y);
            va.z = rna_tf32(va.z); va.w = rna_tf32(va.w);
            *reinterpret_cast<float4*>(As + (fi >> 3) * PAD_A + ((fi & 7) << 2)) = va;
            float4 vb = rb[j];
            float4 vh, vl;
            vh.x = rna_tf32(vb.x); vl.x = rna_tf32(vb.x - vh.x);
            vh.y = rna_tf32(vb.y); vl.y = rna_tf32(vb.y - vh.y);
            vh.z = rna_tf32(vb.z); vl.z = rna_tf32(vb.z - vh.z);
            vh.w = rna_tf32(vb.w); vl.w = rna_tf32(vb.w - vh.w);
            int boff = (fi >> 5) * PAD_B + ((fi & 31) << 2);
            *reinterpret_cast<float4*>(Bh + boff) = vh;
            *reinterpret_cast<float4*>(Bl + boff) = vl;
        }
        __syncthreads();
        if (kt + 1 < KT) {
            const float* Ak = Ag + (size_t)(kt + 1) * BK;
            const float* Bk = Bg + (size_t)(kt + 1) * BK * OO;
#pragma unroll
            for (int j = 0; j < 4; j++) {
                int fi = tid + j * 256;
                ra[j] = *reinterpret_cast<const float4*>(Ak + (size_t)(fi >> 3) * lda + ((fi & 7) << 2));
                rb[j] = *reinterpret_cast<const float4*>(Bk + (size_t)(fi >> 5) * OO + ((fi & 31) << 2));
            }
        }
#pragma unroll
        for (int ks = 0; ks < BK; ks += 8) {
            uint32_t af[4][4], bfh[4][2], bfl[4][2];
#pragma unroll
            for (int mi = 0; mi < 4; mi++) {
                const float* p = As + (wm * 64 + mi * 16 + grp) * PAD_A + ks + tig;
                af[mi][0] = __float_as_uint(p[0]);
                af[mi][1] = __float_as_uint(p[8 * PAD_A]);
                af[mi][2] = __float_as_uint(p[4]);
                af[mi][3] = __float_as_uint(p[8 * PAD_A + 4]);
            }
#pragma unroll
            for (int ni = 0; ni < 4; ni++) {
                int boff = (ks + tig) * PAD_B + wn * 32 + ni * 8 + grp;
                bfh[ni][0] = __float_as_uint(Bh[boff]);
                bfh[ni][1] = __float_as_uint(Bh[boff + 4 * PAD_B]);
                bfl[ni][0] = __float_as_uint(Bl[boff]);
                bfl[ni][1] = __float_as_uint(Bl[boff + 4 * PAD_B]);
            }
#pragma unroll
            for (int mi = 0; mi < 4; mi++)
#pragma unroll
                for (int ni = 0; ni < 4; ni++) {
                    asm volatile(
                        "mma.sync.aligned.m16n8k8.row.col.f32.tf32.tf32.f32 "
                        "{%0,%1,%2,%3}, {%4,%5,%6,%7}, {%8,%9}, {%0,%1,%2,%3};\n"
                        : "+f"(acc[mi][ni][0]), "+f"(acc[mi][ni][1]),
                          "+f"(acc[mi][ni][2]), "+f"(acc[mi][ni][3])
                        : "r"(af[mi][0]), "r"(af[mi][1]), "r"(af[mi][2]), "r"(af[mi][3]),
                          "r"(bfh[ni][0]), "r"(bfh[ni][1]));
                    asm volatile(
                        "mma.sync.aligned.m16n8k8.row.col.f32.tf32.tf32.f32 "
                        "{%0,%1,%2,%3}, {%4,%5,%6,%7}, {%8,%9}, {%0,%1,%2,%3};\n"
                        : "+f"(acc[mi][ni][0]), "+f"(acc[mi][ni][1]),
                          "+f"(acc[mi][ni][2]), "+f"(acc[mi][ni][3])
                        : "r"(af[mi][0]), "r"(af[mi][1]), "r"(af[mi][2]), "r"(af[mi][3]),
                          "r"(bfl[ni][0]), "r"(bfl[ni][1]));
                }
        }
    }

#pragma unroll
    for (int mi = 0; mi < 4; mi++) {
        int row0 = wm * 64 + mi * 16 + grp;
#pragma unroll
        for (int ni = 0; ni < 4; ni++) {
            int col = wn * 32 + ni * 8 + tig * 2;
            *reinterpret_cast<float2*>(Cg + (size_t)row0 * OO + col) =
                make_float2(acc[mi][ni][0], acc[mi][ni][1]);
            *reinterpret_cast<float2*>(Cg + (size_t)(row0 + 8) * OO + col) =
                make_float2(acc[mi][ni][2], acc[mi][ni][3]);
        }
    }
}

// ============ pass 3: gather + self-kernel ============
__global__ void finalize_kernel(const float* __restrict__ he, const int* __restrict__ hidx,
                                const float* __restrict__ te, const int* __restrict__ tidx,
                                const float* __restrict__ sk, float* __restrict__ out) {
    const int b = blockIdx.x;
    const int o = threadIdx.x;
    const bool is_tail = b >= NB;
    const int bb = is_tail ? b - NB : b;
    const float* e = (is_tail ? te : he) + (size_t)bb * DD;
    const int idx = (is_tail ? tidx : hidx)[bb];

    __shared__ float es[DD];
    es[o] = e[o];
    __syncthreads();

    float acc = 0.f;
#pragma unroll
    for (int rr = 0; rr < RR; rr++)
        acc += g_part[((size_t)rr * NN + idx) * OO + o];
#pragma unroll 16
    for (int d = 0; d < DD; ++d)
        acc = fmaf(es[d], sk[d * OO + o], acc);

    out[(size_t)b * OO + o] = acc;
}

extern "C" void kernel_launch(void* const* d_in, const int* in_sizes, int n_in,
                              void* d_out, int out_size) {
    const float* emb  = (const float*)d_in[0];
    const int*   hidx = (const int*)  d_in[1];
    const float* he   = (const float*)d_in[2];
    const int*   tidx = (const int*)  d_in[3];
    const float* te   = (const float*)d_in[4];
    const float* adj  = (const float*)d_in[5];
    const float* rk   = (const float*)d_in[6];
    const float* sk   = (const float*)d_in[7];
    float* out = (float*)d_out;

    float *Wp = nullptr, *Pp = nullptr;
    __half *Whp = nullptr, *Wlp = nullptr;
    cudaGetSymbolAddress((void**)&Wp,  g_W);
    cudaGetSymbolAddress((void**)&Pp,  g_part);
    cudaGetSymbolAddress((void**)&Whp, g_Wth);
    cudaGetSymbolAddress((void**)&Wlp, g_Wtl);

    const size_t smem1 = (size_t)(BM * PAD_A + 2 * BK * PAD_B) * sizeof(float);
    static bool attr_set = false;
    if (!attr_set) {
        cudaFuncSetAttribute(gemm_tf32_split_kernel,
                             cudaFuncAttributeMaxDynamicSharedMemorySize, (int)smem1);
        attr_set = true;
    }

    // Pass 1: W[r] = emb @ rk[r]  (tf32 split, M=4096, K=128)
    gemm_tf32_split_kernel<<<dim3(NN / BM, RR), 256, smem1>>>(
        emb, 0, (size_t)DD,
        rk, (size_t)DD * OO,
        Wp, (size_t)NN * OO,
        DD);

    // Pass 1.5: transpose W -> [r][n][k], split to fp16 hi/lo
    transpose_split_kernel<<<dim3(NN / 32, OO / 32, RR), dim3(32, 8)>>>();

    // Pass 2: g_part[r] = adj[r] @ W[r]  (fp16 mma, B split, 2 terms)
    gemm_fp16_split_kernel<<<dim3(NN / 128, RR), 256>>>(adj, Whp, Wlp, Pp);

    // Pass 3: gather + self-kernel
    finalize_kernel<<<2 * NB, DD>>>(he, hidx, te, tidx, sk, out);
}